// round 12
// baseline (speedup 1.0000x reference)
#include <cuda_runtime.h>
#include <cuda_bf16.h>

// Problem constants (from reference): B=32, T=512, D=768, dur in [0, 8]
#define LR_B 32
#define LR_T 512
#define LR_D 768
#define ZROWS 32   // output rows handled per zero-fill block
#define NTHR 384   // 2 x 192: two source rows per scatter block
#define MAXREPS 8  // dur <= 8.0 -> round(dur) <= 8

// ---------------------------------------------------------------------------
// Single fused kernel. Scatter block (g, b) owns source rows s0=2g, s0+1:
//   threads 0-191 expand row s0, threads 192-383 expand row s0+1. ONE
//   block-wide reduction computes cum[s0+1]; prev for each row follows from
//   two broadcast dur loads. Up to 8 predicated independent float4 streaming
//   stores per thread. Zero-fill blocks reduce tot[b] (unpredicated float4)
//   and zero rows t >= tot in their ZROWS slice (out is 0xAA-poisoned).
// ---------------------------------------------------------------------------
__device__ __forceinline__ int lr_round(float d) {
    return (int)floorf(fmaxf(d, 0.0f) + 0.5f);   // identical fp ops to reference
}

__device__ __forceinline__ int lr_combine(int part, int tid) {
    __shared__ int wsum[NTHR / 32];
    #pragma unroll
    for (int o = 16; o >= 1; o >>= 1) part += __shfl_xor_sync(0xffffffff, part, o);
    if ((tid & 31) == 0) wsum[tid >> 5] = part;
    __syncthreads();
    int c = 0;
    #pragma unroll
    for (int w = 0; w < NTHR / 32; ++w) c += wsum[w];
    return c;
}

__global__ void __launch_bounds__(NTHR) lr_fused_kernel(
    const float* __restrict__ x,
    const float* __restrict__ dur,
    float* __restrict__ out,
    int t_out)
{
    const int b    = blockIdx.y;
    const int tid  = threadIdx.x;
    const int half = tid / 192;            // 0 -> row s0, 1 -> row s0+1
    const int rtid = tid - half * 192;     // float4 lane within the row
    const int stride4 = LR_D / 4;          // 192 float4 per row
    const float* drow = dur + b * LR_T;

    if (blockIdx.x < LR_T / 2) {
        // ------------------- scatter path -------------------
        const int s0 = blockIdx.x * 2;
        const int s  = s0 + half;          // this half's source row

        // Issue this half's source-row load first (hides the reduction).
        const float4* xq = (const float4*)(x + ((size_t)b * LR_T + s) * LR_D) + rtid;
        float4 v;
        asm volatile("ld.global.cs.v4.f32 {%0,%1,%2,%3}, [%4];"
                     : "=f"(v.x), "=f"(v.y), "=f"(v.z), "=f"(v.w)
                     : "l"(xq));

        // ONE reduction for both rows: cum[s0+1] = sum_{j<=s0+1} round(drow[j]).
        int part = 0;
        for (int j = tid; j <= s0 + 1; j += NTHR) part += lr_round(__ldg(drow + j));
        const int cs1 = lr_combine(part, tid);

        const int reps0 = lr_round(__ldg(drow + s0));       // broadcast L1 hits
        const int reps1 = lr_round(__ldg(drow + s0 + 1));
        const int reps  = half ? reps1 : reps0;
        if (reps == 0) return;
        // prev for row s0: cs1 - reps1 - reps0 ; for row s0+1: cs1 - reps1
        const int prev = cs1 - reps1 - (half ? 0 : reps0);

        float4* obase = (float4*)(out + ((size_t)b * t_out + prev) * LR_D) + rtid;
        // reps <= 8: fully unrolled, independent predicated stores (MLP=8).
        #pragma unroll
        for (int r = 0; r < MAXREPS; ++r) {
            if (r < reps) {
                asm volatile("st.global.cs.v4.f32 [%0], {%1,%2,%3,%4};"
                             :: "l"(obase + (size_t)r * stride4),
                                "f"(v.x), "f"(v.y), "f"(v.z), "f"(v.w)
                             : "memory");
            }
        }
    } else {
        // ------------------- zero-fill path -------------------
        // tot[b]: unpredicated float4 reduce of all 512 durations.
        int part = 0;
        if (tid < LR_T / 4) {
            const float4 d = __ldg((const float4*)drow + tid);
            part = lr_round(d.x) + lr_round(d.y) + lr_round(d.z) + lr_round(d.w);
        }
        const int tot = lr_combine(part, tid);

        const int t0 = (blockIdx.x - LR_T / 2) * ZROWS;
        if (t0 + ZROWS <= tot) return;      // fully inside valid region

        const float4 z = make_float4(0.f, 0.f, 0.f, 0.f);
        float4* ob = (float4*)(out + (size_t)b * t_out * LR_D) + rtid;
        // halves interleave over the ZROWS rows
        #pragma unroll 4
        for (int r = half; r < ZROWS; r += 2) {
            const int t = t0 + r;
            if (t >= tot && t < t_out) {
                asm volatile("st.global.cs.v4.f32 [%0], {%1,%2,%3,%4};"
                             :: "l"(ob + (size_t)t * stride4),
                                "f"(z.x), "f"(z.y), "f"(z.z), "f"(z.w)
                             : "memory");
            }
        }
    }
}

// ---------------------------------------------------------------------------
extern "C" void kernel_launch(void* const* d_in, const int* in_sizes, int n_in,
                              void* d_out, int out_size) {
    const float* x   = (const float*)d_in[0];   // [B, T, D] f32
    const float* dur = (const float*)d_in[1];   // [B, T]    f32
    float* out = (float*)d_out;                 // [B, t_out, D] f32

    const int t_out = out_size / (LR_B * LR_D);
    const int zero_blocks = (t_out + ZROWS - 1) / ZROWS;

    dim3 grid(LR_T / 2 + zero_blocks, LR_B);
    lr_fused_kernel<<<grid, NTHR>>>(x, dur, out, t_out);
}

// round 13
// speedup vs baseline: 1.0097x; 1.0097x over previous
#include <cuda_runtime.h>
#include <cuda_bf16.h>

// Problem constants (from reference): B=32, T=512, D=768, dur in [0, 8]
#define LR_B 32
#define LR_T 512
#define LR_D 768
#define ZROWS 32  // output rows handled per zero-fill block
#define NTHR 192
#define MAXREPS 8 // dur <= 8.0 -> round(dur) <= 8

// ---------------------------------------------------------------------------
// FINAL KERNEL (best measured: 43.39us total, 37.8us kernel, 5.31TB/s HBM).
//
// Single fused kernel, one 192-thread block per source row.
//
// Scatter block (s, b): 192 threads issue the x-row streaming load first
//   (hides the prefix reduction under the load's latency), then cooperatively
//   reduce cum[s] = sum_{j<=s} round(dur[b,j]) (scalar strided L2-hot loads,
//   shfl warp-reduce, ONE barrier, sum of 6 warp partials).
//   prev = cum[s] - round(dur[b,s]). Then up to 8 predicated INDEPENDENT
//   float4 streaming stores per thread (reps <= 8 by DUR_MAX -> MLP=8,
//   no loop-control ALU).
//
// Zero-fill block: unpredicated float4 reduction of all 512 durations ->
//   tot[b]; zeroes rows t >= tot in its ZROWS slice (out is 0xAA-poisoned).
//
// ONE launch: no scan kernel, no launch gap, no global scratch. Streaming
// (.cs) stores keep the 206MB output stream from evicting x from L2, so
// steady-state DRAM traffic is write-only -> kernel sits at the measured
// ~5.3TB/s HBM write-path ceiling.
// ---------------------------------------------------------------------------
__device__ __forceinline__ int lr_round(float d) {
    return (int)floorf(fmaxf(d, 0.0f) + 0.5f);   // identical fp ops to reference
}

__device__ __forceinline__ int lr_combine(int part, int tid) {
    __shared__ int wsum[NTHR / 32];
    #pragma unroll
    for (int o = 16; o >= 1; o >>= 1) part += __shfl_xor_sync(0xffffffff, part, o);
    if ((tid & 31) == 0) wsum[tid >> 5] = part;
    __syncthreads();
    int c = 0;
    #pragma unroll
    for (int w = 0; w < NTHR / 32; ++w) c += wsum[w];
    return c;
}

__global__ void __launch_bounds__(NTHR) lr_fused_kernel(
    const float* __restrict__ x,
    const float* __restrict__ dur,
    float* __restrict__ out,
    int t_out)
{
    const int b   = blockIdx.y;
    const int tid = threadIdx.x;
    const int stride4 = LR_D / 4;          // 192 float4 per row
    const float* drow = dur + b * LR_T;

    if (blockIdx.x < LR_T) {
        // ------------------- scatter path -------------------
        const int s = blockIdx.x;

        // Issue the source-row load first (hides the prefix reduction).
        const float4* xq = (const float4*)(x + ((size_t)b * LR_T + s) * LR_D) + tid;
        float4 v;
        asm volatile("ld.global.cs.v4.f32 {%0,%1,%2,%3}, [%4];"
                     : "=f"(v.x), "=f"(v.y), "=f"(v.z), "=f"(v.w)
                     : "l"(xq));

        // cum[s] = sum_{j<=s} round(drow[j]) : strided scalar loads (L2-hot).
        int part = 0;
        for (int j = tid; j <= s; j += NTHR) part += lr_round(__ldg(drow + j));
        const int cs   = lr_combine(part, tid);
        const int reps = lr_round(__ldg(drow + s));   // broadcast L1 hit
        if (reps == 0) return;
        const int prev = cs - reps;

        float4* obase = (float4*)(out + ((size_t)b * t_out + prev) * LR_D) + tid;
        // reps <= 8: fully unrolled, 8 independent predicated stores (MLP=8).
        #pragma unroll
        for (int r = 0; r < MAXREPS; ++r) {
            if (r < reps) {
                asm volatile("st.global.cs.v4.f32 [%0], {%1,%2,%3,%4};"
                             :: "l"(obase + (size_t)r * stride4),
                                "f"(v.x), "f"(v.y), "f"(v.z), "f"(v.w)
                             : "memory");
            }
        }
    } else {
        // ------------------- zero-fill path -------------------
        // tot[b]: unpredicated float4 reduce of all 512 durations.
        int part = 0;
        if (tid < LR_T / 4) {
            const float4 d = __ldg((const float4*)drow + tid);
            part = lr_round(d.x) + lr_round(d.y) + lr_round(d.z) + lr_round(d.w);
        }
        const int tot = lr_combine(part, tid);

        const int t0 = (blockIdx.x - LR_T) * ZROWS;
        if (t0 + ZROWS <= tot) return;      // fully inside valid region

        const float4 z = make_float4(0.f, 0.f, 0.f, 0.f);
        float4* ob = (float4*)(out + (size_t)b * t_out * LR_D) + tid;
        #pragma unroll 4
        for (int r = 0; r < ZROWS; ++r) {
            const int t = t0 + r;
            if (t >= tot && t < t_out) {
                asm volatile("st.global.cs.v4.f32 [%0], {%1,%2,%3,%4};"
                             :: "l"(ob + (size_t)t * stride4),
                                "f"(z.x), "f"(z.y), "f"(z.z), "f"(z.w)
                             : "memory");
            }
        }
    }
}

// ---------------------------------------------------------------------------
extern "C" void kernel_launch(void* const* d_in, const int* in_sizes, int n_in,
                              void* d_out, int out_size) {
    const float* x   = (const float*)d_in[0];   // [B, T, D] f32
    const float* dur = (const float*)d_in[1];   // [B, T]    f32
    float* out = (float*)d_out;                 // [B, t_out, D] f32

    const int t_out = out_size / (LR_B * LR_D);
    const int zero_blocks = (t_out + ZROWS - 1) / ZROWS;

    dim3 grid(LR_T + zero_blocks, LR_B);
    lr_fused_kernel<<<grid, NTHR>>>(x, dur, out, t_out);
}